// round 8
// baseline (speedup 1.0000x reference)
#include <cuda_runtime.h>
#include <math.h>

// MT 1D forward + loss, fused. Output: [total, loss_rhoa, loss_phase].
//
// Layer map on (U,V) (U=N+D, V=N-D, x=Z/Zj normalized):
//   M_j = [[1, -r*E],[r, -E]],  r=(g-1)/(g+1), g=sqrt(rho_j/rho_{j-1})
//   E = exp(-a)(cos a - i sin a), a = s*coef_j, coef_j = t_j*sqrt(2*mu/rho_j)
// Warp-split chains (vector role: deep 11/18 of layers applied to v0;
// matrix role: shallow rest as 2x2 product), combined through shared memory.
//
// KEY (R8): sin/cos computed in the FMA pipe via one packed f32x2 Horner
// (deg-7 in f^2, f = t - rint(t), t = a/2pi <= 2.2) -> 3 MUFU/step reduced
// to 1 (ex2 for exp(-a)). Evidence R4/R6/R7: MUFU-class ops cost ~32
// cyc/op/SMSP on this part and were the binding resource.

#define MUF 1.25663706143591729e-6f   // 4*pi*1e-7
#define TWO_PI_F 6.2831853071795864f
#define INV_2PI_F 0.15915494309189534f
#define NLOG2E_F (-1.4426950408889634f)
#define RAD2DEG_F 57.295779513082321f

__device__ float2 g_part[256];
__device__ unsigned int g_ticket;     // zero-init; last block resets each launch

__device__ __forceinline__ float frcp_fast(float x) {
    float r;
    asm("rcp.approx.ftz.f32 %0, %1;" : "=f"(r) : "f"(x));
    return r;
}
__device__ __forceinline__ float ex2_fast(float x) {
    float r;
    asm("ex2.approx.ftz.f32 %0, %1;" : "=f"(r) : "f"(x));
    return r;
}
__device__ __forceinline__ float frnd_rni(float x) {
    float r;
    asm("cvt.rni.f32.f32 %0, %1;" : "=f"(r) : "f"(x));
    return r;
}
__device__ __forceinline__ unsigned long long f2pack(float lo, float hi) {
    unsigned long long r;
    asm("mov.b64 %0, {%1, %2};" : "=l"(r) : "f"(lo), "f"(hi));
    return r;
}
__device__ __forceinline__ void f2unpack(unsigned long long v, float& lo, float& hi) {
    asm("mov.b64 {%0, %1}, %2;" : "=f"(lo), "=f"(hi) : "l"(v));
}
__device__ __forceinline__ unsigned long long ffma2(unsigned long long a,
                                                    unsigned long long b,
                                                    unsigned long long c) {
    unsigned long long d;
    asm("fma.rn.f32x2 %0, %1, %2, %3;" : "=l"(d) : "l"(a), "l"(b), "l"(c));
    return d;
}

struct SinCosCoef { unsigned long long c[8]; };  // (cos_n, sinpoly_n) pairs

__device__ __forceinline__ SinCosCoef make_coefs() {
    SinCosCoef K;
    K.c[0] = f2pack( 1.0f,          6.28318531f);
    K.c[1] = f2pack(-19.7392088f,  -41.3417022f);
    K.c[2] = f2pack( 64.9393940f,   81.6052492f);
    K.c[3] = f2pack(-85.4568040f,  -76.7058597f);
    K.c[4] = f2pack( 60.2446102f,   42.0586399f);
    K.c[5] = f2pack(-26.4262195f,  -15.0946426f);
    K.c[6] = f2pack(  7.9034587f,    3.8201156f);
    K.c[7] = f2pack( -1.7143695f,   -0.7181223f);
    return K;
}

// E = er - i*ei, er = exp(-a)cos(a), ei = exp(-a)sin(a); a = s*coef.
// s2 = -log2(e)*s (for ex2), s3 = s/(2pi) (for phase). 1 MUFU, rest fma-pipe.
__device__ __forceinline__ void e_math(float coef, float s2, float s3,
                                       const SinCosCoef& K,
                                       float& er, float& ei)
{
    float t  = s3 * coef;              // a / 2pi  (0 .. ~2.2)
    float k  = frnd_rni(t);
    float f  = t - k;                  // [-0.5, 0.5]
    float x2 = f * f;
    unsigned long long xv = f2pack(x2, x2);
    unsigned long long P  = K.c[7];
    P = ffma2(P, xv, K.c[6]);
    P = ffma2(P, xv, K.c[5]);
    P = ffma2(P, xv, K.c[4]);
    P = ffma2(P, xv, K.c[3]);
    P = ffma2(P, xv, K.c[2]);
    P = ffma2(P, xv, K.c[1]);
    P = ffma2(P, xv, K.c[0]);
    float cp, sp;
    f2unpack(P, cp, sp);               // cos(2pi f), sin(2pi f)/f
    float em = ex2_fast(s2 * coef);    // exp(-a)
    er = em * cp;
    ei = (em * f) * sp;
}

__global__ __launch_bounds__(256, 1)
void mt_fused(const float* __restrict__ res,
              const float* __restrict__ thick,
              const float* __restrict__ freq,
              const float* __restrict__ orhoa,
              const float* __restrict__ ophase,
              float* __restrict__ out,
              int nz, int nf, float inv_nf)
{
    __shared__ float2 lay[512];        // (coef_j, r_j), deepest layer first
    __shared__ float4 exch[128];       // vector-warp results
    __shared__ float  sc_x0, sc_lrho0;
    __shared__ float2 red[8];
    __shared__ int    is_last;

    const int nl  = nz - 1;
    const int tid = threadIdx.x;

    for (int i = tid; i < nl; i += blockDim.x) {
        int   j   = nl - 1 - i;                    // deepest first
        float rho = res[j];
        float t   = thick[j];
        float g   = (j >= 1) ? sqrtf(rho / res[j - 1]) : 1.0f;
        lay[i] = make_float2(t * sqrtf(2.0f * MUF / rho),
                             (g - 1.0f) / (g + 1.0f));
    }
    if (tid == 0) {
        sc_x0    = sqrtf(res[nz - 1] / res[nz - 2]);
        sc_lrho0 = log10f(res[0]);
    }
    __syncthreads();

    const int wid  = tid >> 5;
    const int lane = tid & 31;
    const int pair = wid & 3;          // 0..3
    const int role = wid >> 2;         // 0 = vector (deep part), 1 = matrix
    const int fq   = blockIdx.x * 128 + pair * 32 + lane;
    const int vlen = (nl * 11) / 18;   // ~155 for nl=255 (balances role cost)

    float lr = 0.0f, lp = 0.0f;

    float omega = TWO_PI_F * freq[min(fq, nf - 1)];
    float s  = sqrtf(omega);
    float s2 = NLOG2E_F * s;
    float s3 = INV_2PI_F * s;

    SinCosCoef K = make_coefs();

    if (role == 0) {
        // ---- vector warp: deepest vlen layers applied to v0 ----
        float x0 = sc_x0;
        float Ur = x0 + 1.0f, Ui = 0.0f;
        float Vr = x0 - 1.0f, Vi = 0.0f;

        int i = 0;
        for (; i + 8 <= vlen; i += 8) {
            #pragma unroll
            for (int u = 0; u < 8; ++u) {
                float2 L = lay[i + u];
                float er, ei;
                e_math(L.x, s2, s3, K, er, ei);
                float wr = er * Vr + ei * Vi;      // w = E*V
                float wi = er * Vi - ei * Vr;
                float r  = L.y;
                float nUr = fmaf(-r, wr, Ur);
                float nUi = fmaf(-r, wi, Ui);
                float nVr = fmaf( r, Ur, -wr);
                float nVi = fmaf( r, Ui, -wi);
                Ur = nUr; Ui = nUi; Vr = nVr; Vi = nVi;
            }
            float m = frcp_fast(fabsf(Ur) + fabsf(Ui));
            Ur *= m; Ui *= m; Vr *= m; Vi *= m;
        }
        for (; i < vlen; ++i) {
            float2 L = lay[i];
            float er, ei;
            e_math(L.x, s2, s3, K, er, ei);
            float wr = er * Vr + ei * Vi;
            float wi = er * Vi - ei * Vr;
            float r  = L.y;
            float nUr = fmaf(-r, wr, Ur);
            float nUi = fmaf(-r, wi, Ui);
            float nVr = fmaf( r, Ur, -wr);
            float nVi = fmaf( r, Ui, -wi);
            Ur = nUr; Ui = nUi; Vr = nVr; Vi = nVi;
        }
        exch[pair * 32 + lane] = make_float4(Ur, Ui, Vr, Vi);
    } else {
        // ---- matrix warp: layers [vlen, nl) as a 2x2 complex product ----
        float p00r = 1.0f, p00i = 0.0f, p01r = 0.0f, p01i = 0.0f;
        float p10r = 0.0f, p10i = 0.0f, p11r = 1.0f, p11i = 0.0f;

        int i = vlen;
        for (; i + 8 <= nl; i += 8) {
            #pragma unroll
            for (int u = 0; u < 8; ++u) {
                float2 L = lay[i + u];
                float er, ei;
                e_math(L.x, s2, s3, K, er, ei);
                float r = L.y;
                float Xr = er * p10r + ei * p10i;  // X = E*p10 (E = er - i*ei)
                float Xi = er * p10i - ei * p10r;
                float Yr = er * p11r + ei * p11i;  // Y = E*p11
                float Yi = er * p11i - ei * p11r;
                float n00r = fmaf(-r, Xr, p00r);
                float n00i = fmaf(-r, Xi, p00i);
                float n01r = fmaf(-r, Yr, p01r);
                float n01i = fmaf(-r, Yi, p01i);
                float n10r = fmaf( r, p00r, -Xr);
                float n10i = fmaf( r, p00i, -Xi);
                float n11r = fmaf( r, p01r, -Yr);
                float n11i = fmaf( r, p01i, -Yi);
                p00r = n00r; p00i = n00i; p01r = n01r; p01i = n01i;
                p10r = n10r; p10i = n10i; p11r = n11r; p11i = n11i;
            }
            float m = frcp_fast(fabsf(p00r) + fabsf(p00i)
                              + fabsf(p10r) + fabsf(p10i));
            p00r *= m; p00i *= m; p01r *= m; p01i *= m;
            p10r *= m; p10i *= m; p11r *= m; p11i *= m;
        }
        for (; i < nl; ++i) {
            float2 L = lay[i];
            float er, ei;
            e_math(L.x, s2, s3, K, er, ei);
            float r = L.y;
            float Xr = er * p10r + ei * p10i;
            float Xi = er * p10i - ei * p10r;
            float Yr = er * p11r + ei * p11i;
            float Yi = er * p11i - ei * p11r;
            float n00r = fmaf(-r, Xr, p00r);
            float n00i = fmaf(-r, Xi, p00i);
            float n01r = fmaf(-r, Yr, p01r);
            float n01i = fmaf(-r, Yi, p01i);
            float n10r = fmaf( r, p00r, -Xr);
            float n10i = fmaf( r, p00i, -Xi);
            float n11r = fmaf( r, p01r, -Yr);
            float n11i = fmaf( r, p01i, -Yi);
            p00r = n00r; p00i = n00i; p01r = n01r; p01i = n01i;
            p10r = n10r; p10i = n10i; p11r = n11r; p11i = n11i;
        }

        __syncthreads();               // wait for vector warps' exch writes
        if (fq < nf) {
            float4 v  = exch[pair * 32 + lane];
            float Ur = p00r * v.x - p00i * v.y + p01r * v.z - p01i * v.w;
            float Ui = p00r * v.y + p00i * v.x + p01r * v.w + p01i * v.z;
            float Vr = p10r * v.x - p10i * v.y + p11r * v.z - p11i * v.w;
            float Vi = p10r * v.y + p10i * v.x + p11r * v.w + p11i * v.z;

            float Nr = Ur + Vr, Ni = Ui + Vi;
            float Dr = Ur - Vr, Di = Ui - Vi;

            float n2 = fmaxf(Nr * Nr + Ni * Ni, 1e-30f);
            float d2 = fmaxf(Dr * Dr + Di * Di, 1e-30f);
            float A  = Nr * Dr + Ni * Di;
            float B  = Ni * Dr - Nr * Di;

            float e1 = sc_lrho0 + log10f(n2) - log10f(d2) - log10f(orhoa[fq]);
            float ph = atan2f(A + B, A - B) * RAD2DEG_F;
            float e2 = ph - ophase[fq];
            lr = e1 * e1;
            lp = e2 * e2;
        }
    }
    if (role == 0) __syncthreads();    // vector warps join the same barrier

    // deterministic block reduction (8 warps; vector warps contribute 0)
    const unsigned FULL = 0xffffffffu;
    #pragma unroll
    for (int o = 16; o > 0; o >>= 1) {
        lr += __shfl_down_sync(FULL, lr, o);
        lp += __shfl_down_sync(FULL, lp, o);
    }
    if (lane == 0) red[wid] = make_float2(lr, lp);
    __syncthreads();
    if (tid == 0) {
        float slr = 0.0f, slp = 0.0f;
        #pragma unroll
        for (int w = 0; w < 8; ++w) { slr += red[w].x; slp += red[w].y; }
        g_part[blockIdx.x] = make_float2(slr, slp);
        __threadfence();
        unsigned t = atomicAdd(&g_ticket, 1u);
        is_last = (t == gridDim.x - 1) ? 1 : 0;
    }
    __syncthreads();

    if (is_last) {
        __threadfence();
        float flr = 0.0f, flp = 0.0f;
        if (tid < 32) {
            for (int i = tid; i < (int)gridDim.x; i += 32) {
                volatile float* vp = (volatile float*)&g_part[i];
                flr += vp[0];
                flp += vp[1];
            }
            #pragma unroll
            for (int o = 16; o > 0; o >>= 1) {
                flr += __shfl_down_sync(FULL, flr, o);
                flp += __shfl_down_sync(FULL, flp, o);
            }
            if (tid == 0) {
                float mlr = flr * inv_nf;
                float mlp = flp * inv_nf;
                out[0] = mlr + 10.0f * mlp;   // LAMBDA_RHOA=1, LAMBDA_PHASE=10
                out[1] = mlr;
                out[2] = mlp;
                g_ticket = 0;                 // reset for next graph replay
            }
        }
    }
}

extern "C" void kernel_launch(void* const* d_in, const int* in_sizes, int n_in,
                              void* d_out, int out_size)
{
    const float* res = (const float*)d_in[0];
    const float* th  = (const float*)d_in[1];
    const float* fr  = (const float*)d_in[2];
    const float* orh = (const float*)d_in[3];
    const float* oph = (const float*)d_in[4];
    int nz = in_sizes[0];
    int nf = in_sizes[2];

    const int threads = 256;               // 8 warps: 4 vector + 4 matrix
    int blocks = (nf + 127) / 128;         // 128 freqs per block -> 128 blocks
    if (blocks > 256) blocks = 256;

    mt_fused<<<blocks, threads>>>(res, th, fr, orh, oph,
                                  (float*)d_out, nz, nf, 1.0f / (float)nf);
}

// round 9
// speedup vs baseline: 1.0467x; 1.0467x over previous
#include <cuda_runtime.h>
#include <math.h>

// MT 1D forward + loss, fused. Output: [total, loss_rhoa, loss_phase].
//
// Layer map on (U,V) (U=N+D, V=N-D, x=Z/Zj normalized):
//   M_j = [[1, -r*E],[r, -E]],  r=(g-1)/(g+1), g=sqrt(rho_j/rho_{j-1})
//   E = exp(-a)(cos a - i sin a), a = s*coef_j, coef_j = t_j*sqrt(2*mu/rho_j)
//
// R9: 8-way chain split at WARP granularity (divergence-free, unlike R6's
// intra-warp tree). Block = 8 warps x 32 freqs: warp 0 applies the deepest
// 38 layers to v0 (12 FMA/step); warps 1..7 accumulate 31-layer 2x2 products
// (16 FMA/step). Matrix warps publish P via shared; warp 0 applies P1..P7 in
// order and computes the loss. 512 blocks -> 4096 warps (~7/SMSP) to close
// the latency exposure that capped R7/R8 at issue=42%.
// Scale-invariant (renorm every 8 steps); outputs division-free.

#define MUF 1.25663706143591729e-6f   // 4*pi*1e-7
#define TWO_PI_F 6.2831853071795864f
#define RAD2DEG_F 57.295779513082321f

__device__ float2 g_part[512];
__device__ unsigned int g_ticket;     // zero-init; last block resets each launch

__device__ __forceinline__ float frcp_fast(float x) {
    float r;
    asm("rcp.approx.ftz.f32 %0, %1;" : "=f"(r) : "f"(x));
    return r;
}

__device__ __forceinline__ void e_math(float coef, float s,
                                       float& er, float& ei)
{
    float a  = s * coef;
    float em = __expf(-a);
    float sa, ca;
    __sincosf(a, &sa, &ca);
    er = em * ca;                      // E = er - i*ei
    ei = em * sa;
}

__global__ __launch_bounds__(256, 1)
void mt_fused(const float* __restrict__ res,
              const float* __restrict__ thick,
              const float* __restrict__ freq,
              const float* __restrict__ orhoa,
              const float* __restrict__ ophase,
              float* __restrict__ out,
              int nz, int nf, float inv_nf)
{
    __shared__ float2 lay[512];        // (coef_j, r_j), deepest layer first
    __shared__ float  pmat[7][32][8];  // matrix-warp products
    __shared__ float  sc_x0, sc_lrho0;
    __shared__ float2 red[8];
    __shared__ int    is_last;

    const int nl  = nz - 1;
    const int tid = threadIdx.x;

    for (int i = tid; i < nl; i += blockDim.x) {
        int   j   = nl - 1 - i;                    // deepest first
        float rho = res[j];
        float t   = thick[j];
        float g   = (j >= 1) ? sqrtf(rho / res[j - 1]) : 1.0f;
        lay[i] = make_float2(t * sqrtf(2.0f * MUF / rho),
                             (g - 1.0f) / (g + 1.0f));
    }
    if (tid == 0) {
        sc_x0    = sqrtf(res[nz - 1] / res[nz - 2]);
        sc_lrho0 = log10f(res[0]);
    }
    __syncthreads();

    const int wid  = tid >> 5;         // 0..7: 0 = vector role, 1..7 = matrix
    const int lane = tid & 31;
    const int fq   = blockIdx.x * 32 + lane;
    // segment lengths: matrix lm each, vector lv = nl - 7*lm (cost-balanced)
    const int lm   = (nl * 22) / 180;              // 31 for nl=255
    const int lv   = nl - 7 * lm;                  // 38 for nl=255

    float lr = 0.0f, lp = 0.0f;

    float omega = TWO_PI_F * freq[min(fq, nf - 1)];
    float s     = sqrtf(omega);

    if (wid == 0) {
        // ---- vector warp: deepest lv layers applied to v0 ----
        float x0 = sc_x0;
        float Ur = x0 + 1.0f, Ui = 0.0f;
        float Vr = x0 - 1.0f, Vi = 0.0f;

        int i = 0;
        for (; i + 8 <= lv; i += 8) {
            #pragma unroll
            for (int u = 0; u < 8; ++u) {
                float2 L = lay[i + u];
                float er, ei;
                e_math(L.x, s, er, ei);
                float wr = er * Vr + ei * Vi;      // w = E*V
                float wi = er * Vi - ei * Vr;
                float r  = L.y;
                float nUr = fmaf(-r, wr, Ur);
                float nUi = fmaf(-r, wi, Ui);
                float nVr = fmaf( r, Ur, -wr);
                float nVi = fmaf( r, Ui, -wi);
                Ur = nUr; Ui = nUi; Vr = nVr; Vi = nVi;
            }
            float m = frcp_fast(fabsf(Ur) + fabsf(Ui));
            Ur *= m; Ui *= m; Vr *= m; Vi *= m;
        }
        for (; i < lv; ++i) {
            float2 L = lay[i];
            float er, ei;
            e_math(L.x, s, er, ei);
            float wr = er * Vr + ei * Vi;
            float wi = er * Vi - ei * Vr;
            float r  = L.y;
            float nUr = fmaf(-r, wr, Ur);
            float nUi = fmaf(-r, wi, Ui);
            float nVr = fmaf( r, Ur, -wr);
            float nVi = fmaf( r, Ui, -wi);
            Ur = nUr; Ui = nUi; Vr = nVr; Vi = nVi;
        }

        __syncthreads();               // wait for matrix warps' pmat writes

        // apply P1..P7 in layer order, then loss
        #pragma unroll 1
        for (int q = 0; q < 7; ++q) {
            float* P = pmat[q][lane];
            float p00r = P[0], p00i = P[1], p01r = P[2], p01i = P[3];
            float p10r = P[4], p10i = P[5], p11r = P[6], p11i = P[7];
            float nUr = p00r * Ur - p00i * Ui + p01r * Vr - p01i * Vi;
            float nUi = p00r * Ui + p00i * Ur + p01r * Vi + p01i * Vr;
            float nVr = p10r * Ur - p10i * Ui + p11r * Vr - p11i * Vi;
            float nVi = p10r * Ui + p10i * Ur + p11r * Vi + p11i * Vr;
            float m = frcp_fast(fabsf(nUr) + fabsf(nUi));
            Ur = nUr * m; Ui = nUi * m; Vr = nVr * m; Vi = nVi * m;
        }

        if (fq < nf) {
            float Nr = Ur + Vr, Ni = Ui + Vi;
            float Dr = Ur - Vr, Di = Ui - Vi;
            float n2 = fmaxf(Nr * Nr + Ni * Ni, 1e-30f);
            float d2 = fmaxf(Dr * Dr + Di * Di, 1e-30f);
            float A  = Nr * Dr + Ni * Di;
            float B  = Ni * Dr - Nr * Di;
            float e1 = sc_lrho0 + log10f(n2) - log10f(d2) - log10f(orhoa[fq]);
            float ph = atan2f(A + B, A - B) * RAD2DEG_F;
            float e2 = ph - ophase[fq];
            lr = e1 * e1;
            lp = e2 * e2;
        }
    } else {
        // ---- matrix warp wid: layers [lv+(wid-1)*lm, lv+wid*lm) ----
        const int start = lv + (wid - 1) * lm;
        const int end   = start + lm;

        float p00r = 1.0f, p00i = 0.0f, p01r = 0.0f, p01i = 0.0f;
        float p10r = 0.0f, p10i = 0.0f, p11r = 1.0f, p11i = 0.0f;

        int i = start;
        for (; i + 8 <= end; i += 8) {
            #pragma unroll
            for (int u = 0; u < 8; ++u) {
                float2 L = lay[i + u];
                float er, ei;
                e_math(L.x, s, er, ei);
                float r = L.y;
                float Xr = er * p10r + ei * p10i;  // X = E*p10 (E = er - i*ei)
                float Xi = er * p10i - ei * p10r;
                float Yr = er * p11r + ei * p11i;  // Y = E*p11
                float Yi = er * p11i - ei * p11r;
                float n00r = fmaf(-r, Xr, p00r);
                float n00i = fmaf(-r, Xi, p00i);
                float n01r = fmaf(-r, Yr, p01r);
                float n01i = fmaf(-r, Yi, p01i);
                float n10r = fmaf( r, p00r, -Xr);
                float n10i = fmaf( r, p00i, -Xi);
                float n11r = fmaf( r, p01r, -Yr);
                float n11i = fmaf( r, p01i, -Yi);
                p00r = n00r; p00i = n00i; p01r = n01r; p01i = n01i;
                p10r = n10r; p10i = n10i; p11r = n11r; p11i = n11i;
            }
            float m = frcp_fast(fabsf(p00r) + fabsf(p00i)
                              + fabsf(p10r) + fabsf(p10i));
            p00r *= m; p00i *= m; p01r *= m; p01i *= m;
            p10r *= m; p10i *= m; p11r *= m; p11i *= m;
        }
        for (; i < end; ++i) {
            float2 L = lay[i];
            float er, ei;
            e_math(L.x, s, er, ei);
            float r = L.y;
            float Xr = er * p10r + ei * p10i;
            float Xi = er * p10i - ei * p10r;
            float Yr = er * p11r + ei * p11i;
            float Yi = er * p11i - ei * p11r;
            float n00r = fmaf(-r, Xr, p00r);
            float n00i = fmaf(-r, Xi, p00i);
            float n01r = fmaf(-r, Yr, p01r);
            float n01i = fmaf(-r, Yi, p01i);
            float n10r = fmaf( r, p00r, -Xr);
            float n10i = fmaf( r, p00i, -Xi);
            float n11r = fmaf( r, p01r, -Yr);
            float n11i = fmaf( r, p01i, -Yi);
            p00r = n00r; p00i = n00i; p01r = n01r; p01i = n01i;
            p10r = n10r; p10i = n10i; p11r = n11r; p11i = n11i;
        }

        float* P = pmat[wid - 1][lane];
        P[0] = p00r; P[1] = p00i; P[2] = p01r; P[3] = p01i;
        P[4] = p10r; P[5] = p10i; P[6] = p11r; P[7] = p11i;
        __syncthreads();               // publish to vector warp
    }

    // deterministic block reduction (8 warps; only warp 0 is nonzero)
    const unsigned FULL = 0xffffffffu;
    #pragma unroll
    for (int o = 16; o > 0; o >>= 1) {
        lr += __shfl_down_sync(FULL, lr, o);
        lp += __shfl_down_sync(FULL, lp, o);
    }
    if (lane == 0) red[wid] = make_float2(lr, lp);
    __syncthreads();
    if (tid == 0) {
        float slr = 0.0f, slp = 0.0f;
        #pragma unroll
        for (int w = 0; w < 8; ++w) { slr += red[w].x; slp += red[w].y; }
        g_part[blockIdx.x] = make_float2(slr, slp);
        __threadfence();
        unsigned t = atomicAdd(&g_ticket, 1u);
        is_last = (t == gridDim.x - 1) ? 1 : 0;
    }
    __syncthreads();

    if (is_last) {
        __threadfence();
        float flr = 0.0f, flp = 0.0f;
        if (tid < 32) {
            for (int i = tid; i < (int)gridDim.x; i += 32) {
                volatile float* vp = (volatile float*)&g_part[i];
                flr += vp[0];
                flp += vp[1];
            }
            #pragma unroll
            for (int o = 16; o > 0; o >>= 1) {
                flr += __shfl_down_sync(FULL, flr, o);
                flp += __shfl_down_sync(FULL, flp, o);
            }
            if (tid == 0) {
                float mlr = flr * inv_nf;
                float mlp = flp * inv_nf;
                out[0] = mlr + 10.0f * mlp;   // LAMBDA_RHOA=1, LAMBDA_PHASE=10
                out[1] = mlr;
                out[2] = mlp;
                g_ticket = 0;                 // reset for next graph replay
            }
        }
    }
}

extern "C" void kernel_launch(void* const* d_in, const int* in_sizes, int n_in,
                              void* d_out, int out_size)
{
    const float* res = (const float*)d_in[0];
    const float* th  = (const float*)d_in[1];
    const float* fr  = (const float*)d_in[2];
    const float* orh = (const float*)d_in[3];
    const float* oph = (const float*)d_in[4];
    int nz = in_sizes[0];
    int nf = in_sizes[2];

    const int threads = 256;               // 8 warps: 1 vector + 7 matrix
    int blocks = (nf + 31) / 32;           // 32 freqs per block -> 512 blocks
    if (blocks > 512) blocks = 512;

    mt_fused<<<blocks, threads>>>(res, th, fr, orh, oph,
                                  (float*)d_out, nz, nf, 1.0f / (float)nf);
}

// round 10
// speedup vs baseline: 1.0490x; 1.0022x over previous
#include <cuda_runtime.h>
#include <math.h>

// MT 1D forward + loss, fused. Output: [total, loss_rhoa, loss_phase].
//
// R10: f32x2-packed frequency PAIRS. Each thread carries two independent
// frequencies; every FMA of the recurrence is one fma.rn.f32x2 (no cross
// terms between pack halves). Evidence R4/R7/R9: wall time tracks total
// issued instructions at the ~0.5 IPC fma-class issue ceiling; packing
// halves the fma-class slot count.
//
// Layer map on (U,V): M_j = [[1, -r*E],[r, -E]], r=(g-1)/(g+1),
// E = exp(-a)(cos a - i sin a), a = s*coef_j. All updates arranged to use
// only +r by tracking negated products (Xn = -E*p). 8-way warp-split chains
// (1 vector + 7 matrix warps), shared-memory combine, ticket-fused reduction.

typedef unsigned long long u64;

#define MUF 1.25663706143591729e-6f   // 4*pi*1e-7
#define TWO_PI_F 6.2831853071795864f
#define NLOG2E_F (-1.4426950408889634f)
#define RAD2DEG_F 57.295779513082321f

__device__ float2 g_part[512];
__device__ unsigned int g_ticket;     // zero-init; last block resets each launch

__device__ __forceinline__ float frcp_fast(float x) {
    float r; asm("rcp.approx.ftz.f32 %0,%1;" : "=f"(r) : "f"(x)); return r;
}
__device__ __forceinline__ float ex2_fast(float x) {
    float r; asm("ex2.approx.ftz.f32 %0,%1;" : "=f"(r) : "f"(x)); return r;
}
__device__ __forceinline__ u64 ffma2(u64 a, u64 b, u64 c) {
    u64 d; asm("fma.rn.f32x2 %0,%1,%2,%3;" : "=l"(d) : "l"(a), "l"(b), "l"(c)); return d;
}
__device__ __forceinline__ u64 fmul2(u64 a, u64 b) {
    u64 d; asm("mul.rn.f32x2 %0,%1,%2;" : "=l"(d) : "l"(a), "l"(b)); return d;
}
__device__ __forceinline__ u64 fsub2(u64 a, u64 b) {
    u64 d; asm("sub.rn.f32x2 %0,%1,%2;" : "=l"(d) : "l"(a), "l"(b)); return d;
}
__device__ __forceinline__ u64 pk(float lo, float hi) {
    u64 r; asm("mov.b64 %0,{%1,%2};" : "=l"(r) : "f"(lo), "f"(hi)); return r;
}
__device__ __forceinline__ void upk(u64 v, float& lo, float& hi) {
    asm("mov.b64 {%0,%1},%2;" : "=f"(lo), "=f"(hi) : "l"(v));
}

// Packs for the step: NER=(-er), NEI=(-ei), PEI=(+ei) over the freq pair.
// er = exp(-a)cos a, ei = exp(-a)sin a; a = s*coef. Scalar negations fold
// into SASS source modifiers.
__device__ __forceinline__ void e_packs(u64 cc, u64 S, u64 SE,
                                        u64& NER, u64& NEI, u64& PEI)
{
    float aa, ab, ga, gb;
    upk(fmul2(S, cc), aa, ab);
    upk(fmul2(SE, cc), ga, gb);
    float ema = ex2_fast(ga), emb = ex2_fast(gb);
    float sna, csa, snb, csb;
    __sincosf(aa, &sna, &csa);
    __sincosf(ab, &snb, &csb);
    float nma = -ema, nmb = -emb;
    NER = pk(nma * csa, nmb * csb);
    NEI = pk(nma * sna, nmb * snb);
    PEI = pk(ema * sna, emb * snb);
}

__global__ __launch_bounds__(256)
void mt_fused(const float* __restrict__ res,
              const float* __restrict__ thick,
              const float* __restrict__ freq,
              const float* __restrict__ orhoa,
              const float* __restrict__ ophase,
              float* __restrict__ out,
              int nz, int nf, float inv_nf)
{
    __shared__ ulonglong2 layp[512];   // {pk(coef,coef), pk(r,r)}, deepest first
    __shared__ u64  pmat[7][32][9];    // matrix products (9 = bank-conflict pad)
    __shared__ float sc_x0, sc_lrho0;
    __shared__ float2 red[8];
    __shared__ int   is_last;

    const int nl  = nz - 1;
    const int tid = threadIdx.x;

    for (int i = tid; i < nl; i += blockDim.x) {
        int   j    = nl - 1 - i;                   // deepest first
        float rho  = res[j];
        float t    = thick[j];
        float g    = (j >= 1) ? sqrtf(rho / res[j - 1]) : 1.0f;
        float coef = t * sqrtf(2.0f * MUF / rho);
        float r    = (g - 1.0f) / (g + 1.0f);
        layp[i] = make_ulonglong2(pk(coef, coef), pk(r, r));
    }
    if (tid == 0) {
        sc_x0    = sqrtf(res[nz - 1] / res[nz - 2]);
        sc_lrho0 = log10f(res[0]);
    }
    __syncthreads();

    const int wid  = tid >> 5;         // 0 = vector role, 1..7 = matrix
    const int lane = tid & 31;
    const int pidx = blockIdx.x * 32 + lane;       // freq-pair index
    const int pc   = min(pidx, (nf >> 1) - 1);

    int lm = (30 * nl) / 248 + 1;      // matrix segment (31 for nl=255)
    int lv = nl - 7 * lm;              // vector segment (38 for nl=255)
    if (lv < 1) { lm = nl >> 3; lv = nl - 7 * lm; }

    float2 fr2 = ((const float2*)freq)[pc];
    float  ssa = sqrtf(TWO_PI_F * fr2.x);
    float  ssb = sqrtf(TWO_PI_F * fr2.y);
    u64 S  = pk(ssa, ssb);
    u64 SE = pk(NLOG2E_F * ssa, NLOG2E_F * ssb);

    float lr = 0.0f, lp = 0.0f;

    if (wid == 0) {
        // ---- vector warp: deepest lv layers applied to v0 (both freqs) ----
        float x0 = sc_x0;
        u64 Ur = pk(x0 + 1.0f, x0 + 1.0f), Ui = 0;
        u64 Vr = pk(x0 - 1.0f, x0 - 1.0f), Vi = 0;

        int i = 0;
        for (; i + 8 <= lv; i += 8) {
            #pragma unroll
            for (int u = 0; u < 8; ++u) {
                ulonglong2 L = layp[i + u];
                u64 NER, NEI, PEI;
                e_packs(L.x, S, SE, NER, NEI, PEI);
                u64 Wnr = ffma2(NER, Vr, fmul2(NEI, Vi));  // -w
                u64 Wni = ffma2(NER, Vi, fmul2(PEI, Vr));
                u64 nUr = ffma2(L.y, Wnr, Ur);             // U - r*w
                u64 nUi = ffma2(L.y, Wni, Ui);
                u64 nVr = ffma2(L.y, Ur, Wnr);             // r*U - w
                u64 nVi = ffma2(L.y, Ui, Wni);
                Ur = nUr; Ui = nUi; Vr = nVr; Vi = nVi;
            }
            float u0, u1, v0, v1;
            upk(Ur, u0, u1); upk(Ui, v0, v1);
            u64 M = pk(frcp_fast(fabsf(u0) + fabsf(v0)),
                       frcp_fast(fabsf(u1) + fabsf(v1)));
            Ur = fmul2(Ur, M); Ui = fmul2(Ui, M);
            Vr = fmul2(Vr, M); Vi = fmul2(Vi, M);
        }
        for (; i < lv; ++i) {
            ulonglong2 L = layp[i];
            u64 NER, NEI, PEI;
            e_packs(L.x, S, SE, NER, NEI, PEI);
            u64 Wnr = ffma2(NER, Vr, fmul2(NEI, Vi));
            u64 Wni = ffma2(NER, Vi, fmul2(PEI, Vr));
            u64 nUr = ffma2(L.y, Wnr, Ur);
            u64 nUi = ffma2(L.y, Wni, Ui);
            u64 nVr = ffma2(L.y, Ur, Wnr);
            u64 nVi = ffma2(L.y, Ui, Wni);
            Ur = nUr; Ui = nUi; Vr = nVr; Vi = nVi;
        }

        __syncthreads();               // matrix warps published pmat

        #pragma unroll 1
        for (int q = 0; q < 7; ++q) {
            const u64* P = pmat[q][lane];
            u64 a00r = P[0], a00i = P[1], a01r = P[2], a01i = P[3];
            u64 a10r = P[4], a10i = P[5], a11r = P[6], a11i = P[7];
            u64 nUr = fsub2(ffma2(a01r, Vr, fmul2(a00r, Ur)),
                            ffma2(a01i, Vi, fmul2(a00i, Ui)));
            u64 nUi = ffma2(a01i, Vr, ffma2(a01r, Vi,
                      ffma2(a00i, Ur, fmul2(a00r, Ui))));
            u64 nVr = fsub2(ffma2(a11r, Vr, fmul2(a10r, Ur)),
                            ffma2(a11i, Vi, fmul2(a10i, Ui)));
            u64 nVi = ffma2(a11i, Vr, ffma2(a11r, Vi,
                      ffma2(a10i, Ur, fmul2(a10r, Ui))));
            float u0, u1, v0, v1;
            upk(nUr, u0, u1); upk(nUi, v0, v1);
            u64 M = pk(frcp_fast(fabsf(u0) + fabsf(v0)),
                       frcp_fast(fabsf(u1) + fabsf(v1)));
            Ur = fmul2(nUr, M); Ui = fmul2(nUi, M);
            Vr = fmul2(nVr, M); Vi = fmul2(nVi, M);
        }

        // ---- loss for both freqs of the pair ----
        float Ura, Urb, Uia, Uib, Vra, Vrb, Via, Vib;
        upk(Ur, Ura, Urb); upk(Ui, Uia, Uib);
        upk(Vr, Vra, Vrb); upk(Vi, Via, Vib);
        float2 or2 = ((const float2*)orhoa)[pc];
        float2 op2 = ((const float2*)ophase)[pc];
        {
            float Nr = Ura + Vra, Ni = Uia + Via;
            float Dr = Ura - Vra, Di = Uia - Via;
            float n2 = fmaxf(Nr * Nr + Ni * Ni, 1e-30f);
            float d2 = fmaxf(Dr * Dr + Di * Di, 1e-30f);
            float A  = Nr * Dr + Ni * Di;
            float B  = Ni * Dr - Nr * Di;
            float e1 = sc_lrho0 + log10f(n2) - log10f(d2) - log10f(or2.x);
            float e2 = atan2f(A + B, A - B) * RAD2DEG_F - op2.x;
            if (2 * pidx < nf) { lr += e1 * e1; lp += e2 * e2; }
        }
        {
            float Nr = Urb + Vrb, Ni = Uib + Vib;
            float Dr = Urb - Vrb, Di = Uib - Vib;
            float n2 = fmaxf(Nr * Nr + Ni * Ni, 1e-30f);
            float d2 = fmaxf(Dr * Dr + Di * Di, 1e-30f);
            float A  = Nr * Dr + Ni * Di;
            float B  = Ni * Dr - Nr * Di;
            float e1 = sc_lrho0 + log10f(n2) - log10f(d2) - log10f(or2.y);
            float e2 = atan2f(A + B, A - B) * RAD2DEG_F - op2.y;
            if (2 * pidx + 1 < nf) { lr += e1 * e1; lp += e2 * e2; }
        }
    } else {
        // ---- matrix warp wid: layers [lv+(wid-1)*lm, lv+wid*lm) ----
        const int start = lv + (wid - 1) * lm;
        const int end   = start + lm;

        u64 p00r = pk(1, 1), p00i = 0, p01r = 0, p01i = 0;
        u64 p10r = 0, p10i = 0, p11r = pk(1, 1), p11i = 0;

        int i = start;
        for (; i + 8 <= end; i += 8) {
            #pragma unroll
            for (int u = 0; u < 8; ++u) {
                ulonglong2 L = layp[i + u];
                u64 NER, NEI, PEI;
                e_packs(L.x, S, SE, NER, NEI, PEI);
                u64 Xnr = ffma2(NER, p10r, fmul2(NEI, p10i));  // -(E*p10)
                u64 Xni = ffma2(NER, p10i, fmul2(PEI, p10r));
                u64 Ynr = ffma2(NER, p11r, fmul2(NEI, p11i));  // -(E*p11)
                u64 Yni = ffma2(NER, p11i, fmul2(PEI, p11r));
                u64 n00r = ffma2(L.y, Xnr, p00r);
                u64 n00i = ffma2(L.y, Xni, p00i);
                u64 n01r = ffma2(L.y, Ynr, p01r);
                u64 n01i = ffma2(L.y, Yni, p01i);
                u64 n10r = ffma2(L.y, p00r, Xnr);
                u64 n10i = ffma2(L.y, p00i, Xni);
                u64 n11r = ffma2(L.y, p01r, Ynr);
                u64 n11i = ffma2(L.y, p01i, Yni);
                p00r = n00r; p00i = n00i; p01r = n01r; p01i = n01i;
                p10r = n10r; p10i = n10i; p11r = n11r; p11i = n11i;
            }
            float a0, a1, b0, b1;
            upk(p00r, a0, a1); upk(p00i, b0, b1);
            float c0, c1, d0, d1;
            upk(p10r, c0, c1); upk(p10i, d0, d1);
            u64 M = pk(frcp_fast(fabsf(a0) + fabsf(b0) + fabsf(c0) + fabsf(d0)),
                       frcp_fast(fabsf(a1) + fabsf(b1) + fabsf(c1) + fabsf(d1)));
            p00r = fmul2(p00r, M); p00i = fmul2(p00i, M);
            p01r = fmul2(p01r, M); p01i = fmul2(p01i, M);
            p10r = fmul2(p10r, M); p10i = fmul2(p10i, M);
            p11r = fmul2(p11r, M); p11i = fmul2(p11i, M);
        }
        for (; i < end; ++i) {
            ulonglong2 L = layp[i];
            u64 NER, NEI, PEI;
            e_packs(L.x, S, SE, NER, NEI, PEI);
            u64 Xnr = ffma2(NER, p10r, fmul2(NEI, p10i));
            u64 Xni = ffma2(NER, p10i, fmul2(PEI, p10r));
            u64 Ynr = ffma2(NER, p11r, fmul2(NEI, p11i));
            u64 Yni = ffma2(NER, p11i, fmul2(PEI, p11r));
            u64 n00r = ffma2(L.y, Xnr, p00r);
            u64 n00i = ffma2(L.y, Xni, p00i);
            u64 n01r = ffma2(L.y, Ynr, p01r);
            u64 n01i = ffma2(L.y, Yni, p01i);
            u64 n10r = ffma2(L.y, p00r, Xnr);
            u64 n10i = ffma2(L.y, p00i, Xni);
            u64 n11r = ffma2(L.y, p01r, Ynr);
            u64 n11i = ffma2(L.y, p01i, Yni);
            p00r = n00r; p00i = n00i; p01r = n01r; p01i = n01i;
            p10r = n10r; p10i = n10i; p11r = n11r; p11i = n11i;
        }

        u64* P = pmat[wid - 1][lane];
        P[0] = p00r; P[1] = p00i; P[2] = p01r; P[3] = p01i;
        P[4] = p10r; P[5] = p10i; P[6] = p11r; P[7] = p11i;
        __syncthreads();               // publish to vector warp
    }

    // deterministic block reduction (8 warps; only warp 0 nonzero)
    const unsigned FULL = 0xffffffffu;
    #pragma unroll
    for (int o = 16; o > 0; o >>= 1) {
        lr += __shfl_down_sync(FULL, lr, o);
        lp += __shfl_down_sync(FULL, lp, o);
    }
    if (lane == 0) red[wid] = make_float2(lr, lp);
    __syncthreads();
    if (tid == 0) {
        float slr = 0.0f, slp = 0.0f;
        #pragma unroll
        for (int w = 0; w < 8; ++w) { slr += red[w].x; slp += red[w].y; }
        g_part[blockIdx.x] = make_float2(slr, slp);
        __threadfence();
        unsigned t = atomicAdd(&g_ticket, 1u);
        is_last = (t == gridDim.x - 1) ? 1 : 0;
    }
    __syncthreads();

    if (is_last) {
        __threadfence();
        float flr = 0.0f, flp = 0.0f;
        if (tid < 32) {
            for (int i = tid; i < (int)gridDim.x; i += 32) {
                volatile float* vp = (volatile float*)&g_part[i];
                flr += vp[0];
                flp += vp[1];
            }
            #pragma unroll
            for (int o = 16; o > 0; o >>= 1) {
                flr += __shfl_down_sync(FULL, flr, o);
                flp += __shfl_down_sync(FULL, flp, o);
            }
            if (tid == 0) {
                float mlr = flr * inv_nf;
                float mlp = flp * inv_nf;
                out[0] = mlr + 10.0f * mlp;   // LAMBDA_RHOA=1, LAMBDA_PHASE=10
                out[1] = mlr;
                out[2] = mlp;
                g_ticket = 0;                 // reset for next graph replay
            }
        }
    }
}

extern "C" void kernel_launch(void* const* d_in, const int* in_sizes, int n_in,
                              void* d_out, int out_size)
{
    const float* res = (const float*)d_in[0];
    const float* th  = (const float*)d_in[1];
    const float* fr  = (const float*)d_in[2];
    const float* orh = (const float*)d_in[3];
    const float* oph = (const float*)d_in[4];
    int nz = in_sizes[0];
    int nf = in_sizes[2];

    const int threads = 256;               // 8 warps: 1 vector + 7 matrix
    int npairs = nf >> 1;                  // 8192 for NF=16384
    int blocks = (npairs + 31) / 32;       // 256 blocks
    if (blocks > 512) blocks = 512;

    mt_fused<<<blocks, threads>>>(res, th, fr, orh, oph,
                                  (float*)d_out, nz, nf, 1.0f / (float)nf);
}